// round 12
// baseline (speedup 1.0000x reference)
#include <cuda_runtime.h>
#include <cuda_fp16.h>
#include <cstdint>

#define BB 32
#define LL 32768
#define PP 4095
#define DD 128
#define NT 256
#define NCH 16          // K chunks of 32 (total K = 512)
#define RSB 80          // smem row stride bytes (64 data + 16 pad) -> ldmatrix conflict-free
// Stage: A[128*80] Bh[128*80] Bl[128*80] = 30720 B; 2 stages = 61440 B
#define PLB 10240
#define STB 30720

// fp16 hi/lo weight planes, layout [d][c], c = k*32+m (K-major rows)
__device__ __align__(16) __half g_w_hi[128 * 512];
__device__ __align__(16) __half g_w_lo[128 * 512];

__global__ void prep_w_kernel(const float* __restrict__ w)
{
    int i = blockIdx.x * 256 + threadIdx.x;   // 0 .. 65535
    int d = i >> 9, c = i & 511;
    int m = c & 31, kc = c >> 5;
    float v = w[d * 512 + m * 16 + kc];
    __half h = __float2half_rn(v);
    g_w_hi[i] = h;
    g_w_lo[i] = __float2half_rn(v - __half2float(h));
}

#define MMA_F16(D, A, B0, B1)                                             \
    asm volatile("mma.sync.aligned.m16n8k16.row.col.f32.f16.f16.f32 "     \
        "{%0,%1,%2,%3}, {%4,%5,%6,%7}, {%8,%9}, {%0,%1,%2,%3};"           \
        : "+f"((D)[0]), "+f"((D)[1]), "+f"((D)[2]), "+f"((D)[3])          \
        : "r"((A)[0]), "r"((A)[1]), "r"((A)[2]), "r"((A)[3]),             \
          "r"(B0), "r"(B1))

#define LDM_X4(R, ADDR)                                                   \
    asm volatile("ldmatrix.sync.aligned.m8n8.x4.shared.b16 "              \
        "{%0,%1,%2,%3}, [%4];"                                            \
        : "=r"((R)[0]), "=r"((R)[1]), "=r"((R)[2]), "=r"((R)[3])          \
        : "r"(ADDR))

#define CP16(dst, src) \
    asm volatile("cp.async.cg.shared.global [%0], [%1], 16;" :: "r"(dst), "l"(src) : "memory")
#define CP_COMMIT asm volatile("cp.async.commit_group;" ::: "memory")
#define CP_WAIT0  asm volatile("cp.async.wait_group 0;"  ::: "memory")

__device__ __forceinline__ uint32_t smem_u32(const void* p) {
    uint32_t a;
    asm("{ .reg .u64 t; cvta.to.shared.u64 t, %1; cvt.u32.u64 %0, t; }" : "=r"(a) : "l"(p));
    return a;
}

// ---------------------------------------------------------------------------
// HMMA fp16x2 GEMM + bias + PE. CTA 128p x 128d, 8 warps (2m x 4n), warp 64x32.
// x single fp16 plane (LDG+cvt+STS), W hi/lo fp16 planes (cp.async).
// All operand loads via ldmatrix.x4. Double-buffered 32-c chunks.
// ---------------------------------------------------------------------------
__global__ __launch_bounds__(NT, 2)
void pe_mma(const float* __restrict__ x, const float* __restrict__ ts,
            const float* __restrict__ bias, float* __restrict__ out)
{
    extern __shared__ __align__(16) char smem[];
    const uint32_t sb = smem_u32(smem);

    const int tid  = threadIdx.x, wid = tid >> 5, lane = tid & 31;
    const int gid  = lane >> 2, tig = lane & 3;
    const int b    = blockIdx.y;
    const int p0   = blockIdx.x * 128;
    const int wm   = (wid & 1) * 64;   // warp m-base (patches)
    const int wn   = (wid >> 1) * 32;  // warp n-base (d)
    const float* xb = x + (size_t)b * (LL * 32);

    // ldmatrix lane geometry
    const int a_row = (lane & 7) + 8 * ((lane >> 3) & 1);
    const int a_seg = lane >> 4;            // k-half
    const int b_row = (lane & 7) + 8 * (lane >> 4);
    const int b_seg = (lane >> 3) & 1;      // k-half

    float acc[4][4][4];
#pragma unroll
    for (int mt = 0; mt < 4; mt++)
#pragma unroll
        for (int nt = 0; nt < 4; nt++)
#pragma unroll
            for (int q = 0; q < 4; q++) acc[mt][nt][q] = 0.f;

    float4 av[4];

    auto loadA = [&](int ch) {
#pragma unroll
        for (int i = 0; i < 4; i++) {
            int f = tid + i * NT;            // 0..1023: 128 rows x 8 float4
            int row = f >> 3, c4 = f & 7;
            int p = p0 + row;
            av[i] = make_float4(0.f, 0.f, 0.f, 0.f);
            if (p < PP)
                av[i] = *(const float4*)(xb + (size_t)p * 256 + ch * 32 + c4 * 4);
        }
    };
    auto cpB = [&](int ch, int s) {
#pragma unroll
        for (int i = 0; i < 4; i++) {
            int f = tid + i * NT;            // 0..1023
            int plane = f >> 9;              // 0 hi, 1 lo
            int g = f & 511;
            int d = g >> 2, seg = g & 3;     // 4 x 16B per row
            uint32_t dst = sb + s * STB + (1 + plane) * PLB + d * RSB + seg * 16;
            const __half* src = (plane ? g_w_lo : g_w_hi) + d * 512 + ch * 32 + seg * 8;
            CP16(dst, src);
        }
        CP_COMMIT;
    };
    auto stsA = [&](int s) {
        char* Ap = smem + s * STB;
#pragma unroll
        for (int i = 0; i < 4; i++) {
            int f = tid + i * NT;
            int row = f >> 3, c4 = f & 7;
            float4 v = av[i];
            __half2 h01 = __floats2half2_rn(v.x, v.y);
            __half2 h23 = __floats2half2_rn(v.z, v.w);
            *(uint2*)(Ap + row * RSB + c4 * 8) =
                make_uint2(*(uint32_t*)&h01, *(uint32_t*)&h23);
        }
    };

    // ---- prologue: fill stage 0 with chunk 0 ----
    loadA(0);
    cpB(0, 0);
    stsA(0);
    CP_WAIT0;
    __syncthreads();

    for (int ch = 0; ch < NCH; ch++) {
        const int s = ch & 1;
        if (ch + 1 < NCH) {
            loadA(ch + 1);        // LDGs land during compute
            cpB(ch + 1, s ^ 1);
        }

        // ---- compute chunk ch from stage s ----
        {
            const uint32_t Ap = sb + s * STB;
            const uint32_t Bh = Ap + PLB;
            const uint32_t Bl = Ap + 2 * PLB;
#pragma unroll
            for (int t = 0; t < 2; t++) {
                uint32_t a[4][4], bh[2][4], bl[2][4];
#pragma unroll
                for (int mt = 0; mt < 4; mt++)
                    LDM_X4(a[mt], Ap + (wm + mt * 16 + a_row) * RSB + (t * 2 + a_seg) * 16);
#pragma unroll
                for (int j = 0; j < 2; j++) {
                    uint32_t br = (wn + j * 16 + b_row) * RSB + (t * 2 + b_seg) * 16;
                    LDM_X4(bh[j], Bh + br);
                    LDM_X4(bl[j], Bl + br);
                }
#pragma unroll
                for (int nt = 0; nt < 4; nt++) {
                    uint32_t b0h = bh[nt >> 1][(nt & 1) * 2], b1h = bh[nt >> 1][(nt & 1) * 2 + 1];
                    uint32_t b0l = bl[nt >> 1][(nt & 1) * 2], b1l = bl[nt >> 1][(nt & 1) * 2 + 1];
#pragma unroll
                    for (int mt = 0; mt < 4; mt++)
                        MMA_F16(acc[mt][nt], a[mt], b0h, b1h);
#pragma unroll
                    for (int mt = 0; mt < 4; mt++)
                        MMA_F16(acc[mt][nt], a[mt], b0l, b1l);
                }
            }
        }

        if (ch + 1 < NCH) {
            stsA(s ^ 1);
            CP_WAIT0;
        }
        __syncthreads();
    }

    // ---- Epilogue: bias + positional encoding ----
    float  freqs[4];
    float2 bi[4];
#pragma unroll
    for (int nt = 0; nt < 4; nt++) {
        int d0 = wn + nt * 8 + tig * 2;
        freqs[nt] = __expf(-(float)d0 * 0.07195578415606394f);
        bi[nt] = *(const float2*)(bias + d0);
    }
#pragma unroll
    for (int mt = 0; mt < 4; mt++) {
#pragma unroll
        for (int h = 0; h < 2; h++) {
            int p = p0 + wm + mt * 16 + h * 8 + gid;
            if (p < PP) {
                // timestamps sorted along L -> window median = ts[p*8+7]
                float med = ts[(size_t)b * LL + p * 8 + 7];
                float* op = out + ((size_t)b * PP + p) * DD;
#pragma unroll
                for (int nt = 0; nt < 4; nt++) {
                    float s, c;
                    __sincosf(med * freqs[nt], &s, &c);
                    float2 v;
                    v.x = acc[mt][nt][h * 2 + 0] + bi[nt].x + s;
                    v.y = acc[mt][nt][h * 2 + 1] + bi[nt].y + c;
                    *(float2*)(op + wn + nt * 8 + tig * 2) = v;
                }
            }
        }
    }
}

// ---------------------------------------------------------------------------
extern "C" void kernel_launch(void* const* d_in, const int* in_sizes, int n_in,
                              void* d_out, int out_size)
{
    const float* x    = (const float*)d_in[0];   // (B, L, M)
    const float* ts   = (const float*)d_in[1];   // (B, L)
    const float* w    = (const float*)d_in[2];   // (D, M, K)
    const float* bias = (const float*)d_in[3];   // (D,)
    float* out = (float*)d_out;                  // (B, P, D)
    (void)in_sizes; (void)n_in; (void)out_size;

    prep_w_kernel<<<256, 256>>>(w);

    const int smem_bytes = 2 * STB;   // 61440
    cudaFuncSetAttribute(pe_mma,
                         cudaFuncAttributeMaxDynamicSharedMemorySize, smem_bytes);
    dim3 grid(32, BB);   // 32 p-tiles x 32 batches
    pe_mma<<<grid, NT, smem_bytes>>>(x, ts, bias, out);
}

// round 14
// speedup vs baseline: 1.3459x; 1.3459x over previous
#include <cuda_runtime.h>
#include <cuda_fp16.h>
#include <cstdint>

#define BB 32
#define LL 32768
#define PP 4095
#define DD 128
#define NT 256
#define NCH 16          // K chunks of 32 (total K = 512)
#define RSB 80          // smem row stride bytes (64 data + 16 pad) -> ldmatrix conflict-free
// Stage: A[128*80] Bw[128*80] = 20480 B; 2 stages = 40960 B
#define PLB 10240
#define STB 20480

// fp16 weight plane, layout [d][c], c = k*32+m (K-major rows)
__device__ __align__(16) __half g_w[128 * 512];

__global__ void prep_w_kernel(const float* __restrict__ w)
{
    int i = blockIdx.x * 256 + threadIdx.x;   // 0 .. 65535
    int d = i >> 9, c = i & 511;
    int m = c & 31, kc = c >> 5;
    g_w[i] = __float2half_rn(w[d * 512 + m * 16 + kc]);
}

#define MMA_F16(D, A, B0, B1)                                             \
    asm volatile("mma.sync.aligned.m16n8k16.row.col.f32.f16.f16.f32 "     \
        "{%0,%1,%2,%3}, {%4,%5,%6,%7}, {%8,%9}, {%0,%1,%2,%3};"           \
        : "+f"((D)[0]), "+f"((D)[1]), "+f"((D)[2]), "+f"((D)[3])          \
        : "r"((A)[0]), "r"((A)[1]), "r"((A)[2]), "r"((A)[3]),             \
          "r"(B0), "r"(B1))

#define LDM_X4(R, ADDR)                                                   \
    asm volatile("ldmatrix.sync.aligned.m8n8.x4.shared.b16 "              \
        "{%0,%1,%2,%3}, [%4];"                                            \
        : "=r"((R)[0]), "=r"((R)[1]), "=r"((R)[2]), "=r"((R)[3])          \
        : "r"(ADDR))

#define CP16(dst, src) \
    asm volatile("cp.async.cg.shared.global [%0], [%1], 16;" :: "r"(dst), "l"(src) : "memory")
#define CP_COMMIT asm volatile("cp.async.commit_group;" ::: "memory")
#define CP_WAIT0  asm volatile("cp.async.wait_group 0;"  ::: "memory")

__device__ __forceinline__ uint32_t smem_u32(const void* p) {
    uint32_t a;
    asm("{ .reg .u64 t; cvta.to.shared.u64 t, %1; cvt.u32.u64 %0, t; }" : "=r"(a) : "l"(p));
    return a;
}

// ---------------------------------------------------------------------------
// HMMA fp16x1 GEMM + bias + PE. CTA 128p x 128d, 8 warps (4m x 2n), warp 32x64.
// x single fp16 plane (LDG+cvt+STS), W single fp16 plane (cp.async).
// All operand loads via ldmatrix.x4. Double-buffered 32-c chunks.
// ---------------------------------------------------------------------------
__global__ __launch_bounds__(NT, 2)
void pe_mma(const float* __restrict__ x, const float* __restrict__ ts,
            const float* __restrict__ bias, float* __restrict__ out)
{
    extern __shared__ __align__(16) char smem[];
    const uint32_t sb = smem_u32(smem);

    const int tid  = threadIdx.x, wid = tid >> 5, lane = tid & 31;
    const int gid  = lane >> 2, tig = lane & 3;
    const int b    = blockIdx.y;
    const int p0   = blockIdx.x * 128;
    const int wm   = (wid & 3) * 32;   // warp m-base (patches)
    const int wn   = (wid >> 2) * 64;  // warp n-base (d)
    const float* xb = x + (size_t)b * (LL * 32);

    // ldmatrix lane geometry
    const int a_row = (lane & 7) + 8 * ((lane >> 3) & 1);
    const int a_seg = lane >> 4;            // k-half
    const int b_row = (lane & 7) + 8 * (lane >> 4);
    const int b_seg = (lane >> 3) & 1;      // k-half

    float acc[2][8][4];
#pragma unroll
    for (int mt = 0; mt < 2; mt++)
#pragma unroll
        for (int nt = 0; nt < 8; nt++)
#pragma unroll
            for (int q = 0; q < 4; q++) acc[mt][nt][q] = 0.f;

    float4 av[4];

    auto loadA = [&](int ch) {
#pragma unroll
        for (int i = 0; i < 4; i++) {
            int f = tid + i * NT;            // 0..1023: 128 rows x 8 float4
            int row = f >> 3, c4 = f & 7;
            int p = p0 + row;
            av[i] = make_float4(0.f, 0.f, 0.f, 0.f);
            if (p < PP)
                av[i] = *(const float4*)(xb + (size_t)p * 256 + ch * 32 + c4 * 4);
        }
    };
    auto cpB = [&](int ch, int s) {
#pragma unroll
        for (int i = 0; i < 2; i++) {
            int f = tid + i * NT;            // 0..511: 128 rows x 4 seg16
            int d = f >> 2, seg = f & 3;
            uint32_t dst = sb + s * STB + PLB + d * RSB + seg * 16;
            CP16(dst, g_w + d * 512 + ch * 32 + seg * 8);
        }
        CP_COMMIT;
    };
    auto stsA = [&](int s) {
        char* Ap = smem + s * STB;
#pragma unroll
        for (int i = 0; i < 4; i++) {
            int f = tid + i * NT;
            int row = f >> 3, c4 = f & 7;
            float4 v = av[i];
            __half2 h01 = __floats2half2_rn(v.x, v.y);
            __half2 h23 = __floats2half2_rn(v.z, v.w);
            *(uint2*)(Ap + row * RSB + c4 * 8) =
                make_uint2(*(uint32_t*)&h01, *(uint32_t*)&h23);
        }
    };

    // ---- prologue: fill stage 0 with chunk 0 ----
    loadA(0);
    cpB(0, 0);
    stsA(0);
    CP_WAIT0;
    __syncthreads();

    for (int ch = 0; ch < NCH; ch++) {
        const int s = ch & 1;
        if (ch + 1 < NCH) {
            loadA(ch + 1);        // LDGs land during compute
            cpB(ch + 1, s ^ 1);
        }

        // ---- compute chunk ch from stage s ----
        {
            const uint32_t Ap = sb + s * STB;
            const uint32_t Bw = Ap + PLB;
#pragma unroll
            for (int t = 0; t < 2; t++) {
                uint32_t a[2][4], bw[4][4];
#pragma unroll
                for (int mt = 0; mt < 2; mt++)
                    LDM_X4(a[mt], Ap + (wm + mt * 16 + a_row) * RSB + (t * 2 + a_seg) * 16);
#pragma unroll
                for (int j = 0; j < 4; j++)
                    LDM_X4(bw[j], Bw + (wn + j * 16 + b_row) * RSB + (t * 2 + b_seg) * 16);
#pragma unroll
                for (int nt = 0; nt < 8; nt++) {
                    uint32_t b0 = bw[nt >> 1][(nt & 1) * 2];
                    uint32_t b1 = bw[nt >> 1][(nt & 1) * 2 + 1];
                    MMA_F16(acc[0][nt], a[0], b0, b1);
                    MMA_F16(acc[1][nt], a[1], b0, b1);
                }
            }
        }

        if (ch + 1 < NCH) {
            stsA(s ^ 1);
            CP_WAIT0;
        }
        __syncthreads();
    }

    // ---- Epilogue: bias + positional encoding ----
    float  freqs[8];
    float2 bi[8];
#pragma unroll
    for (int nt = 0; nt < 8; nt++) {
        int d0 = wn + nt * 8 + tig * 2;
        freqs[nt] = __expf(-(float)d0 * 0.07195578415606394f);
        bi[nt] = *(const float2*)(bias + d0);
    }
#pragma unroll
    for (int mt = 0; mt < 2; mt++) {
#pragma unroll
        for (int h = 0; h < 2; h++) {
            int p = p0 + wm + mt * 16 + h * 8 + gid;
            if (p < PP) {
                // timestamps sorted along L -> window median = ts[p*8+7]
                float med = ts[(size_t)b * LL + p * 8 + 7];
                float* op = out + ((size_t)b * PP + p) * DD;
#pragma unroll
                for (int nt = 0; nt < 8; nt++) {
                    float s, c;
                    __sincosf(med * freqs[nt], &s, &c);
                    float2 v;
                    v.x = acc[mt][nt][h * 2 + 0] + bi[nt].x + s;
                    v.y = acc[mt][nt][h * 2 + 1] + bi[nt].y + c;
                    *(float2*)(op + wn + nt * 8 + tig * 2) = v;
                }
            }
        }
    }
}

// ---------------------------------------------------------------------------
extern "C" void kernel_launch(void* const* d_in, const int* in_sizes, int n_in,
                              void* d_out, int out_size)
{
    const float* x    = (const float*)d_in[0];   // (B, L, M)
    const float* ts   = (const float*)d_in[1];   // (B, L)
    const float* w    = (const float*)d_in[2];   // (D, M, K)
    const float* bias = (const float*)d_in[3];   // (D,)
    float* out = (float*)d_out;                  // (B, P, D)
    (void)in_sizes; (void)n_in; (void)out_size;

    prep_w_kernel<<<256, 256>>>(w);

    const int smem_bytes = 2 * STB;   // 40960
    cudaFuncSetAttribute(pe_mma,
                         cudaFuncAttributeMaxDynamicSharedMemorySize, smem_bytes);
    dim3 grid(32, BB);   // 32 p-tiles x 32 batches
    pe_mma<<<grid, NT, smem_bytes>>>(x, ts, bias, out);
}